// round 13
// baseline (speedup 1.0000x reference)
#include <cuda_runtime.h>

// KVQuantizerDequantizer: asymmetric 4-bit RTN quantize+dequantize, groups of
// 128 floats along last dim. At the mixed 1:1 r/w DRAM ceiling (~6.43 TB/s).
// This round's single delta vs the converged best: __stwt write-through
// stores — probes whether DRAM read/write turnaround frequency (the ~19%
// DRAM-idle residue) is reducible by pushing writes to the controller in
// issue order (long contiguous bursts) instead of lazy L2 writeback order.
// All other parameters identical to the best-measured config.

#define MAXQ 15.0f
#define EPS 1e-8f

__global__ void __launch_bounds__(256, 8)
kvq_kernel(const float* __restrict__ x, float* __restrict__ out, unsigned n_groups) {
    const unsigned lane = threadIdx.x & 31u;
    const unsigned sl   = lane & 7u;            // lane within 8-lane octet
    const unsigned warp_global = blockIdx.x * (blockDim.x >> 5) + (threadIdx.x >> 5);
    const unsigned group = warp_global * 4u + (lane >> 3);
    if (group >= n_groups) return;

    const float4* gp = reinterpret_cast<const float4*>(x) + (size_t)group * 32u;

    // 4 independent loads, front-batched (MLP=4)
    float4 a = gp[sl];
    float4 b = gp[sl + 8];
    float4 c = gp[sl + 16];
    float4 d = gp[sl + 24];

    // local min/max over 16 values
    float mn = fminf(fminf(fminf(a.x, a.y), fminf(a.z, a.w)),
                     fminf(fminf(b.x, b.y), fminf(b.z, b.w)));
    mn = fminf(mn, fminf(fminf(fminf(c.x, c.y), fminf(c.z, c.w)),
                         fminf(fminf(d.x, d.y), fminf(d.z, d.w))));
    float mx = fmaxf(fmaxf(fmaxf(a.x, a.y), fmaxf(a.z, a.w)),
                     fmaxf(fmaxf(b.x, b.y), fmaxf(b.z, b.w)));
    mx = fmaxf(mx, fmaxf(fmaxf(fmaxf(c.x, c.y), fmaxf(c.z, c.w)),
                         fmaxf(fmaxf(d.x, d.y), fmaxf(d.z, d.w))));

    // butterfly within the 8-lane octet (xor 1,2,4 stays inside)
    #pragma unroll
    for (int off = 1; off < 8; off <<= 1) {
        mn = fminf(mn, __shfl_xor_sync(0xffffffffu, mn, off));
        mx = fmaxf(mx, __shfl_xor_sync(0xffffffffu, mx, off));
    }

    // scale / offset (CLIP_RATIO = 1.0); one true division per thread
    const float scale  = fmaxf((mx - mn) / MAXQ, EPS);
    const float rscale = 1.0f / scale;
    const float offset = rintf(-mn * rscale);

    // quantize + dequantize (rintf == jnp.round: round-half-to-even under RN)
    #define QDQ(e) do { \
        float q = fminf(fmaxf(rintf((e) * rscale) + offset, 0.0f), MAXQ); \
        (e) = (q - offset) * scale; \
    } while (0)
    QDQ(a.x); QDQ(a.y); QDQ(a.z); QDQ(a.w);
    QDQ(b.x); QDQ(b.y); QDQ(b.z); QDQ(b.w);
    QDQ(c.x); QDQ(c.y); QDQ(c.z); QDQ(c.w);
    QDQ(d.x); QDQ(d.y); QDQ(d.z); QDQ(d.w);
    #undef QDQ

    float4* og = reinterpret_cast<float4*>(out) + (size_t)group * 32u;
    __stwt(&og[sl],      a);
    __stwt(&og[sl + 8],  b);
    __stwt(&og[sl + 16], c);
    __stwt(&og[sl + 24], d);
}

extern "C" void kernel_launch(void* const* d_in, const int* in_sizes, int n_in,
                              void* d_out, int out_size) {
    const float* x = (const float*)d_in[0];
    float* out = (float*)d_out;

    unsigned n_groups = (unsigned)((long long)in_sizes[0] / 128);  // 524288

    const int threads = 256;                   // 8 warps -> 32 groups per block
    unsigned groups_per_block = (threads / 32) * 4;
    unsigned blocks = (n_groups + groups_per_block - 1) / groups_per_block;

    kvq_kernel<<<blocks, threads>>>(x, out, n_groups);
}

// round 14
// speedup vs baseline: 1.0047x; 1.0047x over previous
#include <cuda_runtime.h>

// KVQuantizerDequantizer: asymmetric 4-bit RTN quantize+dequantize, groups of
// 128 floats along last dim. FINAL — converged at the mixed 1:1 read/write
// DRAM ceiling (6.40-6.45 TB/s; 537 MB mandatory traffic in ~74.5us kernel
// time, zero wasted bytes; residual DRAM-idle is controller-level bank
// turnaround, proven invisible to wb/cs/wt store policy).
//
// Convergence evidence (13 rounds, every axis single-variable tested):
//   MLP 1/4/8 | occupancy 48-84% | block 128/256 | loads ca/cg/cs |
//   stores wb/cs/wt | 128b/256b accesses | multi-wave/persistent/SW-pipelined
// All non-regressive configs clamp at the same bandwidth; persistent variants
// regressed 8-11% (they defeat the CTA scheduler's free load/store overlap).
//
// Best-measured config (bench 81.98us x2, ncu 74.43us):
//  - non-persistent launch, 16384 x 256 threads
//  - 8 lanes per group, 4 groups per warp, 4 front-batched float4 loads (MLP=4)
//  - default-cached loads, plain writeback stores
//  - 32 regs, occupancy 8 blocks/SM

#define MAXQ 15.0f
#define EPS 1e-8f

__global__ void __launch_bounds__(256, 8)
kvq_kernel(const float* __restrict__ x, float* __restrict__ out, unsigned n_groups) {
    const unsigned lane = threadIdx.x & 31u;
    const unsigned sl   = lane & 7u;            // lane within 8-lane octet
    const unsigned warp_global = blockIdx.x * (blockDim.x >> 5) + (threadIdx.x >> 5);
    const unsigned group = warp_global * 4u + (lane >> 3);
    if (group >= n_groups) return;

    const float4* gp = reinterpret_cast<const float4*>(x) + (size_t)group * 32u;

    // 4 independent loads, front-batched (MLP=4)
    float4 a = gp[sl];
    float4 b = gp[sl + 8];
    float4 c = gp[sl + 16];
    float4 d = gp[sl + 24];

    // local min/max over 16 values
    float mn = fminf(fminf(fminf(a.x, a.y), fminf(a.z, a.w)),
                     fminf(fminf(b.x, b.y), fminf(b.z, b.w)));
    mn = fminf(mn, fminf(fminf(fminf(c.x, c.y), fminf(c.z, c.w)),
                         fminf(fminf(d.x, d.y), fminf(d.z, d.w))));
    float mx = fmaxf(fmaxf(fmaxf(a.x, a.y), fmaxf(a.z, a.w)),
                     fmaxf(fmaxf(b.x, b.y), fmaxf(b.z, b.w)));
    mx = fmaxf(mx, fmaxf(fmaxf(fmaxf(c.x, c.y), fmaxf(c.z, c.w)),
                         fmaxf(fmaxf(d.x, d.y), fmaxf(d.z, d.w))));

    // butterfly within the 8-lane octet (xor 1,2,4 stays inside)
    #pragma unroll
    for (int off = 1; off < 8; off <<= 1) {
        mn = fminf(mn, __shfl_xor_sync(0xffffffffu, mn, off));
        mx = fmaxf(mx, __shfl_xor_sync(0xffffffffu, mx, off));
    }

    // scale / offset (CLIP_RATIO = 1.0); one true division per thread
    const float scale  = fmaxf((mx - mn) / MAXQ, EPS);
    const float rscale = 1.0f / scale;
    const float offset = rintf(-mn * rscale);

    // quantize + dequantize (rintf == jnp.round: round-half-to-even under RN)
    #define QDQ(e) do { \
        float q = fminf(fmaxf(rintf((e) * rscale) + offset, 0.0f), MAXQ); \
        (e) = (q - offset) * scale; \
    } while (0)
    QDQ(a.x); QDQ(a.y); QDQ(a.z); QDQ(a.w);
    QDQ(b.x); QDQ(b.y); QDQ(b.z); QDQ(b.w);
    QDQ(c.x); QDQ(c.y); QDQ(c.z); QDQ(c.w);
    QDQ(d.x); QDQ(d.y); QDQ(d.z); QDQ(d.w);
    #undef QDQ

    float4* og = reinterpret_cast<float4*>(out) + (size_t)group * 32u;
    og[sl]      = a;
    og[sl + 8]  = b;
    og[sl + 16] = c;
    og[sl + 24] = d;
}

extern "C" void kernel_launch(void* const* d_in, const int* in_sizes, int n_in,
                              void* d_out, int out_size) {
    const float* x = (const float*)d_in[0];
    float* out = (float*)d_out;

    unsigned n_groups = (unsigned)((long long)in_sizes[0] / 128);  // 524288

    const int threads = 256;                   // 8 warps -> 32 groups per block
    unsigned groups_per_block = (threads / 32) * 4;
    unsigned blocks = (n_groups + groups_per_block - 1) / groups_per_block;

    kvq_kernel<<<blocks, threads>>>(x, out, n_groups);
}

// round 15
// speedup vs baseline: 1.0051x; 1.0004x over previous
#include <cuda_runtime.h>

// KVQuantizerDequantizer: asymmetric 4-bit RTN quantize+dequantize, groups of
// 128 floats along last dim. At the mixed 1:1 r/w DRAM ceiling (~6.45 TB/s,
// 537 MB mandatory traffic, ~74us kernel time).
// This round closes the final untested axis: 512-thread CTAs (occupancy 4).
// Same per-warp geometry as the converged best (8 lanes/group, 4 groups/warp,
// 4 front-batched float4 loads, 32 regs, 64 warps/SM) — only CTA granularity
// changes: 64 front-batched LDGs per CTA arrive as larger contiguous bursts,
// and CTA count halves (8192), trimming tail-wave launch overhead.

#define MAXQ 15.0f
#define EPS 1e-8f

__global__ void __launch_bounds__(512, 4)
kvq_kernel(const float* __restrict__ x, float* __restrict__ out, unsigned n_groups) {
    const unsigned lane = threadIdx.x & 31u;
    const unsigned sl   = lane & 7u;            // lane within 8-lane octet
    const unsigned warp_global = blockIdx.x * (blockDim.x >> 5) + (threadIdx.x >> 5);
    const unsigned group = warp_global * 4u + (lane >> 3);
    if (group >= n_groups) return;

    const float4* gp = reinterpret_cast<const float4*>(x) + (size_t)group * 32u;

    // 4 independent loads, front-batched (MLP=4)
    float4 a = gp[sl];
    float4 b = gp[sl + 8];
    float4 c = gp[sl + 16];
    float4 d = gp[sl + 24];

    // local min/max over 16 values
    float mn = fminf(fminf(fminf(a.x, a.y), fminf(a.z, a.w)),
                     fminf(fminf(b.x, b.y), fminf(b.z, b.w)));
    mn = fminf(mn, fminf(fminf(fminf(c.x, c.y), fminf(c.z, c.w)),
                         fminf(fminf(d.x, d.y), fminf(d.z, d.w))));
    float mx = fmaxf(fmaxf(fmaxf(a.x, a.y), fmaxf(a.z, a.w)),
                     fmaxf(fmaxf(b.x, b.y), fmaxf(b.z, b.w)));
    mx = fmaxf(mx, fmaxf(fmaxf(fmaxf(c.x, c.y), fmaxf(c.z, c.w)),
                         fmaxf(fmaxf(d.x, d.y), fmaxf(d.z, d.w))));

    // butterfly within the 8-lane octet (xor 1,2,4 stays inside)
    #pragma unroll
    for (int off = 1; off < 8; off <<= 1) {
        mn = fminf(mn, __shfl_xor_sync(0xffffffffu, mn, off));
        mx = fmaxf(mx, __shfl_xor_sync(0xffffffffu, mx, off));
    }

    // scale / offset (CLIP_RATIO = 1.0); one true division per thread
    const float scale  = fmaxf((mx - mn) / MAXQ, EPS);
    const float rscale = 1.0f / scale;
    const float offset = rintf(-mn * rscale);

    // quantize + dequantize (rintf == jnp.round: round-half-to-even under RN)
    #define QDQ(e) do { \
        float q = fminf(fmaxf(rintf((e) * rscale) + offset, 0.0f), MAXQ); \
        (e) = (q - offset) * scale; \
    } while (0)
    QDQ(a.x); QDQ(a.y); QDQ(a.z); QDQ(a.w);
    QDQ(b.x); QDQ(b.y); QDQ(b.z); QDQ(b.w);
    QDQ(c.x); QDQ(c.y); QDQ(c.z); QDQ(c.w);
    QDQ(d.x); QDQ(d.y); QDQ(d.z); QDQ(d.w);
    #undef QDQ

    float4* og = reinterpret_cast<float4*>(out) + (size_t)group * 32u;
    og[sl]      = a;
    og[sl + 8]  = b;
    og[sl + 16] = c;
    og[sl + 24] = d;
}

extern "C" void kernel_launch(void* const* d_in, const int* in_sizes, int n_in,
                              void* d_out, int out_size) {
    const float* x = (const float*)d_in[0];
    float* out = (float*)d_out;

    unsigned n_groups = (unsigned)((long long)in_sizes[0] / 128);  // 524288

    const int threads = 512;                   // 16 warps -> 64 groups per block
    unsigned groups_per_block = (threads / 32) * 4;
    unsigned blocks = (n_groups + groups_per_block - 1) / groups_per_block;

    kvq_kernel<<<blocks, threads>>>(x, out, n_groups);
}